// round 7
// baseline (speedup 1.0000x reference)
#include <cuda_runtime.h>
#include <math.h>

#define Bsz   2
#define Sq    4096
#define HIDd  2048
#define NHh   32
#define NKVh  8
#define Rrows (Bsz*Sq)            // 8192

// ---------------- scratch (static device globals; no allocation) ----------------
__device__ float g_Qp  [(size_t)Rrows*2048];   // [B*S, NH*64]   rope+kappa in place
__device__ float g_Kp  [(size_t)Rrows*512];    // [B*S, NKV*64]  rope+kappa in place
__device__ float g_Vp  [(size_t)Rrows*512];
__device__ float g_Xphi[(size_t)Rrows*2048];
__device__ float g_ctx [(size_t)Rrows*2048];
__device__ float g_Qg  [64*64];                // [bh, d]
__device__ float g_alpha[(size_t)64*Sq];       // [bh, s]  (logits, then alpha in place)
__device__ float g_M   [(size_t)64*64*64];     // [bh, d, f]

// ---------------- plain fp32 GEMM: C[M,N] = A[M,K] * B[K,N], all row-major ----
// (cross-validated across two independent implementations in earlier rounds)
__global__ __launch_bounds__(256)
void gemm64(const float* __restrict__ A, const float* __restrict__ B,
            float* __restrict__ C, int M, int N, int K)
{
    __shared__ float As[32][68];
    __shared__ float Bs[32][64];
    const int tid = threadIdx.x;
    const int bm = blockIdx.y * 64;
    const int bn = blockIdx.x * 64;
    const int ty = tid >> 4;
    const int tx = tid & 15;

    float acc[4][4] = {};
    const int nk = K / 32;
    for (int kt = 0; kt < nk; kt++) {
        const int kb = kt * 32;
        float4 av[2], bv[2];
#pragma unroll
        for (int i = 0; i < 2; i++) {
            const int lin = tid + i * 256;
            const int arow = lin >> 3;
            const int akc  = (lin & 7) * 4;
            av[i] = *(const float4*)(A + (size_t)(bm + arow) * K + kb + akc);
            const int bkr = lin >> 4;
            const int bnc = (lin & 15) * 4;
            bv[i] = *(const float4*)(B + (size_t)(kb + bkr) * N + bn + bnc);
        }
        __syncthreads();
#pragma unroll
        for (int i = 0; i < 2; i++) {
            const int lin = tid + i * 256;
            const int arow = lin >> 3;
            const int akc  = (lin & 7) * 4;
            As[akc+0][arow] = av[i].x; As[akc+1][arow] = av[i].y;
            As[akc+2][arow] = av[i].z; As[akc+3][arow] = av[i].w;
            const int bkr = lin >> 4;
            const int bnc = (lin & 15) * 4;
            *(float4*)&Bs[bkr][bnc] = bv[i];
        }
        __syncthreads();
#pragma unroll 8
        for (int k = 0; k < 32; k++) {
            float4 a4 = *(const float4*)&As[k][ty*4];
            float4 b4 = *(const float4*)&Bs[k][tx*4];
            float ar[4] = {a4.x, a4.y, a4.z, a4.w};
            float br[4] = {b4.x, b4.y, b4.z, b4.w};
#pragma unroll
            for (int i = 0; i < 4; i++)
#pragma unroll
                for (int j = 0; j < 4; j++) acc[i][j] = fmaf(ar[i], br[j], acc[i][j]);
        }
    }
#pragma unroll
    for (int i = 0; i < 4; i++) {
        const size_t r = bm + ty*4 + i;
#pragma unroll
        for (int j = 0; j < 4; j++)
            C[r * N + bn + tx*4 + j] = acc[i][j];
    }
}

// ================= NAIVE rewrites of previously-shared kernels ==================

// RoPE + kappa, in place. Layout [R, H, 64]. One thread per (r, h, d<32) pair.
// Index decomposition via div/mod (different from previous shift/mask version).
__global__ void rope_kappa_naive(float* __restrict__ X, int H, int total_pairs)
{
    const int idx = blockIdx.x * blockDim.x + threadIdx.x;
    if (idx >= total_pairs) return;
    const int d = idx % 32;
    const int t = idx / 32;
    const int h = t % H;
    const int r = t / H;
    const int s = r % Sq;
    float* p = X + ((size_t)r * H + h) * 64;
    const float x1 = p[d], x2 = p[d + 32];
    // mimic reference f32 pipeline: inv_freq = 1/10000^(2d/64); angle = s*inv (f32)
    const float invf = 1.0f / powf(10000.0f, (2.0f * (float)d) / 64.0f);
    const float ang = (float)s * invf;
    const float c = cosf(ang), sn = sinf(ang);
    const float o1 = x1 * c - x2 * sn;
    const float o2 = x2 * c + x1 * sn;
    p[d]      = o1 > 0.f ? o1 + 1.f : expf(o1);   // elu(x)+1
    p[d + 32] = o2 > 0.f ? o2 + 1.f : expf(o2);
}

// Qg[bh, d] = mean_s Qp[(b*Sq+s)*2048 + n*64 + d]. One thread per (bh, d).
__global__ void qg_naive(void)
{
    const int idx = blockIdx.x * blockDim.x + threadIdx.x;   // 0..4095
    if (idx >= 64 * 64) return;
    const int bh = idx / 64, d = idx % 64;
    const int b = bh / NHh, n = bh % NHh;
    float sum = 0.f;
    for (int s = 0; s < Sq; s++)
        sum += g_Qp[((size_t)(b * Sq + s)) * 2048 + n * 64 + d];
    g_Qg[idx] = sum / (float)Sq;
}

// logits[bh, s] = sum_d Qg[bh,d] * Kk[b, n/4, s, d]. One thread per (bh, s).
__global__ void logits_naive(void)
{
    const int idx = blockIdx.x * blockDim.x + threadIdx.x;   // 0..64*Sq-1
    if (idx >= 64 * Sq) return;
    const int s = idx % Sq, bh = idx / Sq;
    const int b = bh / NHh, n = bh % NHh, kn = n / 4;
    const float* row = g_Kp + ((size_t)(b * Sq + s)) * 512 + kn * 64;
    const float* qg  = g_Qg + bh * 64;
    float acc = 0.f;
    for (int d = 0; d < 64; d++) acc += row[d] * qg[d];
    g_alpha[idx] = acc;
}

// softmax over s (in place on g_alpha), times Sq. One block per bh.
__global__ __launch_bounds__(256) void softmax_naive(void)
{
    const int bh = blockIdx.x;
    float* l = g_alpha + (size_t)bh * Sq;
    __shared__ float sh[256];
    const int tid = threadIdx.x;
    float m = -1e30f;
    for (int s = tid; s < Sq; s += 256) m = fmaxf(m, l[s]);
    sh[tid] = m;
    __syncthreads();
    for (int st = 128; st; st >>= 1) {
        if (tid < st) sh[tid] = fmaxf(sh[tid], sh[tid + st]);
        __syncthreads();
    }
    m = sh[0];
    __syncthreads();
    float sum = 0.f;
    for (int s = tid; s < Sq; s += 256) sum += expf(l[s] - m);
    sh[tid] = sum;
    __syncthreads();
    for (int st = 128; st; st >>= 1) {
        if (tid < st) sh[tid] += sh[tid + st];
        __syncthreads();
    }
    const float scale = (float)Sq / sh[0];
    for (int s = tid; s < Sq; s += 256) l[s] = expf(l[s] - m) * scale;
}

// M[bh, d, f] = sum_s alpha[bh,s] * Kk[b,kn,s,d] * V[b,kn,s,f].
// One thread per (bh, d, f).
__global__ void outer_naive(void)
{
    const int idx = blockIdx.x * blockDim.x + threadIdx.x;   // 0..262143
    if (idx >= 64 * 64 * 64) return;
    const int f = idx & 63, d = (idx >> 6) & 63, bh = idx >> 12;
    const int b = bh / NHh, n = bh % NHh, kn = n / 4;
    const float* al = g_alpha + (size_t)bh * Sq;
    float acc = 0.f;
    for (int s = 0; s < Sq; s++) {
        const size_t base = ((size_t)(b * Sq + s)) * 512 + kn * 64;
        acc += al[s] * g_Kp[base + d] * g_Vp[base + f];
    }
    g_M[idx] = acc;
}

// ctx[r, n*64+f] = Xphi[r, n*64+f] * sum_d Qp[r, n*64+d] * M[bh, d, f].
// One thread per output element.
__global__ void apply_naive(void)
{
    const size_t idx = (size_t)blockIdx.x * blockDim.x + threadIdx.x;
    if (idx >= (size_t)Rrows * 2048) return;
    const int c = (int)(idx % 2048);
    const size_t r = idx / 2048;
    const int n = c >> 6, f = c & 63;
    const int b = (int)(r / Sq);
    const int bh = b * NHh + n;
    const float* q = g_Qp + r * 2048 + n * 64;
    const float* m = g_M + (size_t)bh * 4096;   // [d][f]
    float acc = 0.f;
    for (int d = 0; d < 64; d++) acc += q[d] * m[d * 64 + f];
    g_ctx[idx] = acc * g_Xphi[idx];
}

// ---------------- launch ----------------
extern "C" void kernel_launch(void* const* d_in, const int* in_sizes, int n_in,
                              void* d_out, int out_size)
{
    // size-based identification (position-agnostic; resolves to insertion order here)
    int hidx = -1, w4[3], n4 = 0, w1[2], n1 = 0;
    for (int i = 0; i < n_in; i++) {
        if (in_sizes[i] == 16777216) hidx = i;
        else if (in_sizes[i] == 4194304 && n4 < 3) w4[n4++] = i;
        else if (in_sizes[i] == 1048576 && n1 < 2) w1[n1++] = i;
    }
    const bool alpha_order = (w1[0] < w4[0]);   // alphabetical vs insertion
    const float* h    = (const float*)d_in[hidx];
    const float* Wq   = (const float*)d_in[alpha_order ? w4[2] : w4[0]];
    const float* Wphi = (const float*)d_in[w4[1]];
    const float* Wo   = (const float*)d_in[alpha_order ? w4[0] : w4[2]];
    const float* Wk   = (const float*)d_in[w1[0]];
    const float* Wv   = (const float*)d_in[w1[1]];
    float* out = (float*)d_out;

    // device-global scratch referenced directly by kernels; only GEMM takes pointers,
    // obtained via cudaGetSymbolAddress-free mechanism: pass symbol addresses through
    // kernels that use them directly. For gemm64 we still need raw pointers:
    static float *Qp = nullptr, *Kp = nullptr, *Vp = nullptr, *Xphi = nullptr, *ctx = nullptr;
    if (!Qp) {
        cudaGetSymbolAddress((void**)&Qp,   g_Qp);
        cudaGetSymbolAddress((void**)&Kp,   g_Kp);
        cudaGetSymbolAddress((void**)&Vp,   g_Vp);
        cudaGetSymbolAddress((void**)&Xphi, g_Xphi);
        cudaGetSymbolAddress((void**)&ctx,  g_ctx);
    }

    const dim3 thr(256);

    // projections (natural [B*S, cols] layout)
    gemm64<<<dim3(2048/64, Rrows/64), thr>>>(h, Wq,   Qp,   Rrows, 2048, 2048);
    gemm64<<<dim3( 512/64, Rrows/64), thr>>>(h, Wk,   Kp,   Rrows,  512, 2048);
    gemm64<<<dim3( 512/64, Rrows/64), thr>>>(h, Wv,   Vp,   Rrows,  512, 2048);
    gemm64<<<dim3(2048/64, Rrows/64), thr>>>(h, Wphi, Xphi, Rrows, 2048, 2048);

    // rope + kappa (in place)
    {
        const int totQ = Rrows * NHh  * 32;
        const int totK = Rrows * NKVh * 32;
        rope_kappa_naive<<<(totQ + 255)/256, 256>>>(Qp, NHh,  totQ);
        rope_kappa_naive<<<(totK + 255)/256, 256>>>(Kp, NKVh, totK);
    }

    qg_naive<<<(64*64 + 255)/256, 256>>>();
    logits_naive<<<(64*Sq + 255)/256, 256>>>();
    softmax_naive<<<64, 256>>>();
    outer_naive<<<(64*64*64 + 255)/256, 256>>>();
    apply_naive<<<(int)(((size_t)Rrows*2048 + 255)/256), 256>>>();

    // output projection
    gemm64<<<dim3(2048/64, Rrows/64), thr>>>(ctx, Wo, out, Rrows, 2048, 2048);
}

// round 8
// speedup vs baseline: 1.4141x; 1.4141x over previous
#include <cuda_runtime.h>
#include <math.h>

#define Bsz   2
#define Sq    4096
#define HIDd  2048
#define NHh   32
#define NKVh  8
#define Rrows (Bsz*Sq)            // 8192
#define OSPL  8

// ---------------- scratch (static device globals; no allocation) ----------------
__device__ float g_Qp  [(size_t)Rrows*2048];   // [B*S, NH*64]   rope+kappa in place
__device__ float g_Kp  [(size_t)Rrows*512];    // [B*S, NKV*64]  rope+kappa in place
__device__ float g_Vp  [(size_t)Rrows*512];
__device__ float g_Xphi[(size_t)Rrows*2048];
__device__ float g_ctx [(size_t)Rrows*2048];
__device__ float g_Qg  [64*64];                // [bh, d]
__device__ float g_alpha[(size_t)64*Sq];       // [bh, s]  (logits, then alpha in place)
__device__ float g_Mpart[(size_t)OSPL*64*64*64];
__device__ float g_M   [(size_t)64*64*64];     // [bh, d, f]

// ---------------- fp32 GEMM: C[M,N] = A[M,K] * B[K,N], row-major ----------------
// 128x128 tile, BK=16, 256 threads, 8x8 microtile (4+4 split rows/cols),
// double-buffered shared memory.
__global__ __launch_bounds__(256, 2)
void gemm128(const float* __restrict__ A, const float* __restrict__ B,
             float* __restrict__ C, int M, int N, int K)
{
    __shared__ float As[2][16][132];   // [buf][k][m]
    __shared__ float Bs[2][16][128];   // [buf][k][n]
    const int tid = threadIdx.x;
    const int bm = blockIdx.y * 128;
    const int bn = blockIdx.x * 128;
    const int ty = tid >> 4;           // 0..15
    const int tx = tid & 15;           // 0..15

    // global->smem load indices
    const int arow = tid >> 2;         // 0..63 (second half +64)
    const int acol = (tid & 3) * 4;    // 0,4,8,12
    const int brow = tid >> 5;         // 0..7  (second half +8)
    const int bcol = (tid & 31) * 4;   // 0..124

    float acc[8][8] = {};
    float4 a0, a1, b0, b1;

    // prologue: tile 0
    a0 = *(const float4*)(A + (size_t)(bm + arow)      * K + acol);
    a1 = *(const float4*)(A + (size_t)(bm + arow + 64) * K + acol);
    b0 = *(const float4*)(B + (size_t)(brow)     * N + bn + bcol);
    b1 = *(const float4*)(B + (size_t)(brow + 8) * N + bn + bcol);
    As[0][acol+0][arow] = a0.x; As[0][acol+1][arow] = a0.y;
    As[0][acol+2][arow] = a0.z; As[0][acol+3][arow] = a0.w;
    As[0][acol+0][arow+64] = a1.x; As[0][acol+1][arow+64] = a1.y;
    As[0][acol+2][arow+64] = a1.z; As[0][acol+3][arow+64] = a1.w;
    *(float4*)&Bs[0][brow][bcol]   = b0;
    *(float4*)&Bs[0][brow+8][bcol] = b1;
    __syncthreads();

    const int nk = K / 16;
    for (int kt = 0; kt < nk; kt++) {
        const int cur = kt & 1;
        const bool more = (kt + 1 < nk);
        if (more) {
            const int kb = (kt + 1) * 16;
            a0 = *(const float4*)(A + (size_t)(bm + arow)      * K + kb + acol);
            a1 = *(const float4*)(A + (size_t)(bm + arow + 64) * K + kb + acol);
            b0 = *(const float4*)(B + (size_t)(kb + brow)     * N + bn + bcol);
            b1 = *(const float4*)(B + (size_t)(kb + brow + 8) * N + bn + bcol);
        }
#pragma unroll
        for (int k = 0; k < 16; k++) {
            float ar[8], br[8];
            *(float4*)&ar[0] = *(const float4*)&As[cur][k][ty*4];
            *(float4*)&ar[4] = *(const float4*)&As[cur][k][ty*4 + 64];
            *(float4*)&br[0] = *(const float4*)&Bs[cur][k][tx*4];
            *(float4*)&br[4] = *(const float4*)&Bs[cur][k][tx*4 + 64];
#pragma unroll
            for (int i = 0; i < 8; i++)
#pragma unroll
                for (int j = 0; j < 8; j++)
                    acc[i][j] = fmaf(ar[i], br[j], acc[i][j]);
        }
        if (more) {
            const int nxt = cur ^ 1;
            As[nxt][acol+0][arow] = a0.x; As[nxt][acol+1][arow] = a0.y;
            As[nxt][acol+2][arow] = a0.z; As[nxt][acol+3][arow] = a0.w;
            As[nxt][acol+0][arow+64] = a1.x; As[nxt][acol+1][arow+64] = a1.y;
            As[nxt][acol+2][arow+64] = a1.z; As[nxt][acol+3][arow+64] = a1.w;
            *(float4*)&Bs[nxt][brow][bcol]   = b0;
            *(float4*)&Bs[nxt][brow+8][bcol] = b1;
            __syncthreads();
        }
    }

#pragma unroll
    for (int i = 0; i < 8; i++) {
        const int row = bm + ((i < 4) ? (ty*4 + i) : (64 + ty*4 + i - 4));
        float4 c0 = {acc[i][0], acc[i][1], acc[i][2], acc[i][3]};
        float4 c1 = {acc[i][4], acc[i][5], acc[i][6], acc[i][7]};
        *(float4*)(C + (size_t)row * N + bn + tx*4)      = c0;
        *(float4*)(C + (size_t)row * N + bn + tx*4 + 64) = c1;
    }
}

// ---------------- RoPE + kappa (validated naive, in place) ----------------
__global__ void rope_kappa_naive(float* __restrict__ X, int H, int total_pairs)
{
    const int idx = blockIdx.x * blockDim.x + threadIdx.x;
    if (idx >= total_pairs) return;
    const int d = idx % 32;
    const int t = idx / 32;
    const int h = t % H;
    const int r = t / H;
    const int s = r % Sq;
    float* p = X + ((size_t)r * H + h) * 64;
    const float x1 = p[d], x2 = p[d + 32];
    const float invf = 1.0f / powf(10000.0f, (2.0f * (float)d) / 64.0f);
    const float ang = (float)s * invf;
    const float c = cosf(ang), sn = sinf(ang);
    const float o1 = x1 * c - x2 * sn;
    const float o2 = x2 * c + x1 * sn;
    p[d]      = o1 > 0.f ? o1 + 1.f : expf(o1);
    p[d + 32] = o2 > 0.f ? o2 + 1.f : expf(o2);
}

// ---------------- Qg[bh,d] = mean_s Qp[(b*Sq+s)*2048 + n*64 + d] ----------------
__global__ __launch_bounds__(256) void qg_tile(void)
{
    const int bh = blockIdx.x;            // 0..63
    const int b = bh / NHh, n = bh % NHh;
    const int d = threadIdx.x & 63, rr = threadIdx.x >> 6;   // rr 0..3
    float sum = 0.f;
    for (int s = rr; s < Sq; s += 4)
        sum += g_Qp[((size_t)(b * Sq + s)) * 2048 + n * 64 + d];
    __shared__ float sm[4][64];
    sm[rr][d] = sum;
    __syncthreads();
    if (threadIdx.x < 64) {
        const int dd = threadIdx.x;
        g_Qg[bh * 64 + dd] =
            (sm[0][dd] + sm[1][dd] + sm[2][dd] + sm[3][dd]) / (float)Sq;
    }
}

// ---------------- logits (validated naive) ----------------
__global__ void logits_naive(void)
{
    const int idx = blockIdx.x * blockDim.x + threadIdx.x;
    if (idx >= 64 * Sq) return;
    const int s = idx % Sq, bh = idx / Sq;
    const int b = bh / NHh, n = bh % NHh, kn = n / 4;
    const float* row = g_Kp + ((size_t)(b * Sq + s)) * 512 + kn * 64;
    const float* qg  = g_Qg + bh * 64;
    float acc = 0.f;
    for (int d = 0; d < 64; d++) acc += row[d] * qg[d];
    g_alpha[idx] = acc;
}

// ---------------- softmax * Sq (validated naive, in place) ----------------
__global__ __launch_bounds__(256) void softmax_naive(void)
{
    const int bh = blockIdx.x;
    float* l = g_alpha + (size_t)bh * Sq;
    __shared__ float sh[256];
    const int tid = threadIdx.x;
    float m = -1e30f;
    for (int s = tid; s < Sq; s += 256) m = fmaxf(m, l[s]);
    sh[tid] = m;
    __syncthreads();
    for (int st = 128; st; st >>= 1) {
        if (tid < st) sh[tid] = fmaxf(sh[tid], sh[tid + st]);
        __syncthreads();
    }
    m = sh[0];
    __syncthreads();
    float sum = 0.f;
    for (int s = tid; s < Sq; s += 256) sum += expf(l[s] - m);
    sh[tid] = sum;
    __syncthreads();
    for (int st = 128; st; st >>= 1) {
        if (tid < st) sh[tid] += sh[tid + st];
        __syncthreads();
    }
    const float scale = (float)Sq / sh[0];
    for (int s = tid; s < Sq; s += 256) l[s] = expf(l[s] - m) * scale;
}

// ---------------- outer partials: tiled rewrite of validated outer_naive -------
// Mpart[split][bh][d][f] = sum_{s in split} alpha[bh,s]*Kk[b,kn,s,d]*V[b,kn,s,f]
__global__ __launch_bounds__(256) void outer_tile(void)
{
    const int split = blockIdx.x, bh = blockIdx.y;
    const int b = bh / NHh, n = bh % NHh, kn = n / 4;
    const float* al = g_alpha + (size_t)bh * Sq;
    __shared__ float Ks[32][68];
    __shared__ float Vs[32][68];
    const int tid = threadIdx.x;
    const int d0 = (tid >> 4) * 4, f0 = (tid & 15) * 4;
    // loader indices: 32 rows x 64 cols = 2048 floats; 256 thr x 8 floats
    const int sr = tid >> 3;           // 0..31
    const int c8 = (tid & 7) * 8;      // 0,8,..,56
    float acc[4][4] = {};
    const int s_begin = split * (Sq / OSPL);
    const int s_end   = s_begin + (Sq / OSPL);
    for (int s0 = s_begin; s0 < s_end; s0 += 32) {
        __syncthreads();
        {
            const float a = al[s0 + sr];
            const size_t base = ((size_t)(b * Sq + s0 + sr)) * 512 + kn * 64 + c8;
            float4 k0 = *(const float4*)(g_Kp + base);
            float4 k1 = *(const float4*)(g_Kp + base + 4);
            float4 v0 = *(const float4*)(g_Vp + base);
            float4 v1 = *(const float4*)(g_Vp + base + 4);
            k0.x *= a; k0.y *= a; k0.z *= a; k0.w *= a;
            k1.x *= a; k1.y *= a; k1.z *= a; k1.w *= a;
            *(float4*)&Ks[sr][c8]     = k0;
            *(float4*)&Ks[sr][c8 + 4] = k1;
            *(float4*)&Vs[sr][c8]     = v0;
            *(float4*)&Vs[sr][c8 + 4] = v1;
        }
        __syncthreads();
#pragma unroll 8
        for (int ss = 0; ss < 32; ss++) {
            float4 k4 = *(const float4*)&Ks[ss][d0];
            float4 v4 = *(const float4*)&Vs[ss][f0];
            float kr[4] = {k4.x, k4.y, k4.z, k4.w};
            float vr[4] = {v4.x, v4.y, v4.z, v4.w};
#pragma unroll
            for (int i = 0; i < 4; i++)
#pragma unroll
                for (int j = 0; j < 4; j++)
                    acc[i][j] = fmaf(kr[i], vr[j], acc[i][j]);
        }
    }
    float* Mo = g_Mpart + ((size_t)split * 64 + bh) * 4096;
#pragma unroll
    for (int i = 0; i < 4; i++)
#pragma unroll
        for (int j = 0; j < 4; j++)
            Mo[(d0 + i) * 64 + (f0 + j)] = acc[i][j];
}

__global__ void reduce_M(void)
{
    const int idx = blockIdx.x * blockDim.x + threadIdx.x;
    if (idx >= 64 * 4096) return;
    float s = 0.f;
#pragma unroll
    for (int k = 0; k < OSPL; k++) s += g_Mpart[(size_t)k * 64 * 4096 + idx];
    g_M[idx] = s;
}

// ---------------- apply: ctx = Xphi * (Qk @ M), float4 over f ----------------
__global__ void apply_vec4(void)
{
    const size_t q4 = (size_t)blockIdx.x * blockDim.x + threadIdx.x;
    if (q4 >= (size_t)Rrows * 2048 / 4) return;
    const size_t e = q4 * 4;
    const int c = (int)(e % 2048);
    const size_t r = e / 2048;
    const int n = c >> 6, f0 = c & 63;
    const int b = (int)(r / Sq);
    const int bh = b * NHh + n;
    const float* q = g_Qp + r * 2048 + n * 64;
    const float* m = g_M + (size_t)bh * 4096;   // [d][f]
    float4 acc = {0.f, 0.f, 0.f, 0.f};
#pragma unroll 8
    for (int d = 0; d < 64; d++) {
        const float qd = q[d];
        float4 m4 = *(const float4*)(m + d * 64 + f0);
        acc.x = fmaf(qd, m4.x, acc.x);
        acc.y = fmaf(qd, m4.y, acc.y);
        acc.z = fmaf(qd, m4.z, acc.z);
        acc.w = fmaf(qd, m4.w, acc.w);
    }
    float4 xp = *(const float4*)(g_Xphi + e);
    acc.x *= xp.x; acc.y *= xp.y; acc.z *= xp.z; acc.w *= xp.w;
    *(float4*)(g_ctx + e) = acc;
}

// ---------------- launch ----------------
extern "C" void kernel_launch(void* const* d_in, const int* in_sizes, int n_in,
                              void* d_out, int out_size)
{
    // size-based identification (validated: resolves insertion order correctly)
    int hidx = -1, w4[3], n4 = 0, w1[2], n1 = 0;
    for (int i = 0; i < n_in; i++) {
        if (in_sizes[i] == 16777216) hidx = i;
        else if (in_sizes[i] == 4194304 && n4 < 3) w4[n4++] = i;
        else if (in_sizes[i] == 1048576 && n1 < 2) w1[n1++] = i;
    }
    const bool alpha_order = (w1[0] < w4[0]);
    const float* h    = (const float*)d_in[hidx];
    const float* Wq   = (const float*)d_in[alpha_order ? w4[2] : w4[0]];
    const float* Wphi = (const float*)d_in[w4[1]];
    const float* Wo   = (const float*)d_in[alpha_order ? w4[0] : w4[2]];
    const float* Wk   = (const float*)d_in[w1[0]];
    const float* Wv   = (const float*)d_in[w1[1]];
    float* out = (float*)d_out;

    static float *Qp = nullptr, *Kp = nullptr, *Vp = nullptr, *Xphi = nullptr, *ctx = nullptr;
    if (!Qp) {
        cudaGetSymbolAddress((void**)&Qp,   g_Qp);
        cudaGetSymbolAddress((void**)&Kp,   g_Kp);
        cudaGetSymbolAddress((void**)&Vp,   g_Vp);
        cudaGetSymbolAddress((void**)&Xphi, g_Xphi);
        cudaGetSymbolAddress((void**)&ctx,  g_ctx);
    }

    const dim3 thr(256);

    // projections (natural [B*S, cols] layout)
    gemm128<<<dim3(2048/128, Rrows/128), thr>>>(h, Wq,   Qp,   Rrows, 2048, 2048);
    gemm128<<<dim3( 512/128, Rrows/128), thr>>>(h, Wk,   Kp,   Rrows,  512, 2048);
    gemm128<<<dim3( 512/128, Rrows/128), thr>>>(h, Wv,   Vp,   Rrows,  512, 2048);
    gemm128<<<dim3(2048/128, Rrows/128), thr>>>(h, Wphi, Xphi, Rrows, 2048, 2048);

    // rope + kappa (in place)
    {
        const int totQ = Rrows * NHh  * 32;
        const int totK = Rrows * NKVh * 32;
        rope_kappa_naive<<<(totQ + 255)/256, 256>>>(Qp, NHh,  totQ);
        rope_kappa_naive<<<(totK + 255)/256, 256>>>(Kp, NKVh, totK);
    }

    qg_tile<<<64, 256>>>();
    logits_naive<<<(64*Sq + 255)/256, 256>>>();
    softmax_naive<<<64, 256>>>();

    outer_tile<<<dim3(OSPL, 64), thr>>>();
    reduce_M<<<(64*4096 + 255)/256, 256>>>();

    apply_vec4<<<(int)(((size_t)Rrows*2048/4 + 255)/256), 256>>>();

    // output projection
    gemm128<<<dim3(2048/128, Rrows/128), thr>>>(ctx, Wo, out, Rrows, 2048, 2048);
}

// round 17
// speedup vs baseline: 2.7142x; 1.9194x over previous
#include <cuda_runtime.h>
#include <cuda_bf16.h>
#include <math.h>
#include <stdint.h>

#define Bsz   2
#define Sq    4096
#define NHh   32
#define NKVh  8
#define Rrows (Bsz*Sq)            // 8192
#define KT    2048
#define OSPL  8

// ---------------- scratch (static device globals; no allocation) ----------------
__device__ float g_Qp  [(size_t)Rrows*2048];
__device__ float g_Kp  [(size_t)Rrows*512];
__device__ float g_Vp  [(size_t)Rrows*512];
__device__ float g_Xphi[(size_t)Rrows*2048];
__device__ float g_Qg  [64*64];
__device__ float g_alpha[(size_t)64*Sq];
__device__ float g_Mpart[(size_t)OSPL*64*64*64];
__device__ float g_M   [(size_t)64*64*64];

// bf16 split operands
__device__ __nv_bfloat16 g_hh  [(size_t)Rrows*KT];
__device__ __nv_bfloat16 g_hl  [(size_t)Rrows*KT];
__device__ __nv_bfloat16 g_ctxh[(size_t)Rrows*KT];
__device__ __nv_bfloat16 g_ctxl[(size_t)Rrows*KT];
__device__ __nv_bfloat16 g_Wqth[(size_t)2048*KT], g_Wqtl[(size_t)2048*KT];
__device__ __nv_bfloat16 g_Wkth[(size_t)512*KT],  g_Wktl[(size_t)512*KT];
__device__ __nv_bfloat16 g_Wvth[(size_t)512*KT],  g_Wvtl[(size_t)512*KT];
__device__ __nv_bfloat16 g_Wpth[(size_t)2048*KT], g_Wptl[(size_t)2048*KT];
__device__ __nv_bfloat16 g_Woth[(size_t)2048*KT], g_Wotl[(size_t)2048*KT];

// ---------------- warp-level bf16 MMA (baseline PTX, works on sm_103) ----------
__device__ __forceinline__ void mma_bf16(float* d, const uint32_t* a, const uint32_t* b)
{
    asm volatile(
        "mma.sync.aligned.m16n8k16.row.col.f32.bf16.bf16.f32 "
        "{%0,%1,%2,%3}, {%4,%5,%6,%7}, {%8,%9}, {%0,%1,%2,%3};"
        : "+f"(d[0]), "+f"(d[1]), "+f"(d[2]), "+f"(d[3])
        : "r"(a[0]), "r"(a[1]), "r"(a[2]), "r"(a[3]), "r"(b[0]), "r"(b[1]));
}

// ---------------- HMMA GEMM: C[M,N] = A[M,K] * Bt[N,K]^T, K=2048 -------------
// A, Bt given as bf16 hi/lo. 3-pass split (hh + hl + lh) in fp32 accumulators.
// CTA: 128x128 tile, 256 thr = 8 warps (2x4), each warp 64x32.
// Smem/chunk: 4 tiles [128 rows][32 bf16] as u32[128][20] (16 data + 4 pad).
// Double-buffered: 2 x 40KB.
__global__ __launch_bounds__(256, 1)
void gemm_mma(const __nv_bfloat16* __restrict__ Ah, const __nv_bfloat16* __restrict__ Al,
              const __nv_bfloat16* __restrict__ Bh, const __nv_bfloat16* __restrict__ Bl,
              float* __restrict__ C, int N)
{
    extern __shared__ uint32_t smbuf[];      // [2][10240] u32
    const int tid = threadIdx.x;
    const int wid = tid >> 5, lane = tid & 31;
    const int bm = blockIdx.y * 128, bn = blockIdx.x * 128;
    const int wm = (wid & 1) * 64, wn = (wid >> 1) * 32;
    const int lr = lane >> 2, lc = lane & 3;

    float acc[4][4][4] = {};
    uint4 st[8];

    const int srow0 = tid >> 2;              // 0..63 (pass 1 adds 64)
    const int sq    = tid & 3;               // uint4 index within 64B row

#define STAGE_LOAD(kb) do { \
    _Pragma("unroll") \
    for (int _p = 0; _p < 2; _p++) { \
        const int _r = srow0 + _p * 64; \
        const size_t _oa = (size_t)(bm + _r) * KT + (kb) + sq * 8; \
        const size_t _ob = (size_t)(bn + _r) * KT + (kb) + sq * 8; \
        st[0 + _p] = *(const uint4*)(Ah + _oa); \
        st[2 + _p] = *(const uint4*)(Al + _oa); \
        st[4 + _p] = *(const uint4*)(Bh + _ob); \
        st[6 + _p] = *(const uint4*)(Bl + _ob); \
    } \
} while (0)

#define STAGE_STORE(buf) do { \
    uint32_t* _b = smbuf + (buf) * 10240; \
    _Pragma("unroll") \
    for (int _p = 0; _p < 2; _p++) { \
        const int _r = srow0 + _p * 64; \
        *(uint4*)(_b +        _r * 20 + sq * 4) = st[0 + _p]; \
        *(uint4*)(_b + 2560 + _r * 20 + sq * 4) = st[2 + _p]; \
        *(uint4*)(_b + 5120 + _r * 20 + sq * 4) = st[4 + _p]; \
        *(uint4*)(_b + 7680 + _r * 20 + sq * 4) = st[6 + _p]; \
    } \
} while (0)

    STAGE_LOAD(0);
    STAGE_STORE(0);
    __syncthreads();

    const int nchunk = KT / 32;              // 64
    for (int kt = 0; kt < nchunk; kt++) {
        const int cur = kt & 1;
        if (kt + 1 < nchunk) STAGE_LOAD((kt + 1) * 32);

        const uint32_t* b_ = smbuf + cur * 10240;
#pragma unroll
        for (int ks = 0; ks < 2; ks++) {
            uint32_t bh[4][2], bl[4][2];
#pragma unroll
            for (int nt = 0; nt < 4; nt++) {
                const int na = (wn + nt * 8 + lr) * 20 + ks * 8 + lc;
                bh[nt][0] = b_[5120 + na]; bh[nt][1] = b_[5120 + na + 4];
                bl[nt][0] = b_[7680 + na]; bl[nt][1] = b_[7680 + na + 4];
            }
#pragma unroll
            for (int mt = 0; mt < 4; mt++) {
                const int ma = (wm + mt * 16 + lr) * 20 + ks * 8 + lc;
                uint32_t ah[4] = { b_[ma], b_[ma + 160], b_[ma + 4], b_[ma + 164] };
                uint32_t al4[4] = { b_[2560 + ma], b_[2560 + ma + 160],
                                    b_[2560 + ma + 4], b_[2560 + ma + 164] };
#pragma unroll
                for (int nt = 0; nt < 4; nt++) {
                    mma_bf16(acc[mt][nt], ah,  bh[nt]);
                    mma_bf16(acc[mt][nt], ah,  bl[nt]);
                    mma_bf16(acc[mt][nt], al4, bh[nt]);
                }
            }
        }

        if (kt + 1 < nchunk) {
            STAGE_STORE(cur ^ 1);
            __syncthreads();
        }
    }

    // epilogue
#pragma unroll
    for (int mt = 0; mt < 4; mt++) {
        const int r0 = bm + wm + mt * 16 + lr;
#pragma unroll
        for (int nt = 0; nt < 4; nt++) {
            const int c0 = bn + wn + nt * 8 + lc * 2;
            *(float2*)(C + (size_t)r0 * N + c0)       = make_float2(acc[mt][nt][0], acc[mt][nt][1]);
            *(float2*)(C + (size_t)(r0 + 8) * N + c0) = make_float2(acc[mt][nt][2], acc[mt][nt][3]);
        }
    }
#undef STAGE_LOAD
#undef STAGE_STORE
}

// ---------------- bf16 split converters ----------------
__global__ void split_bf16(const float* __restrict__ X, __nv_bfloat16* __restrict__ H,
                           __nv_bfloat16* __restrict__ L, size_t n)
{
    const size_t i = (size_t)blockIdx.x * blockDim.x + threadIdx.x;
    if (i >= n) return;
    const float x = X[i];
    const __nv_bfloat16 h = __float2bfloat16(x);
    H[i] = h;
    L[i] = __float2bfloat16(x - __bfloat162float(h));
}

// W [KT, N] fp32 -> Wt hi/lo [N, KT] bf16 (smem-tiled transpose)
__global__ void splitT_bf16(const float* __restrict__ W, __nv_bfloat16* __restrict__ TH,
                            __nv_bfloat16* __restrict__ TL, int Ncols)
{
    __shared__ float t[32][33];
    const int bx = blockIdx.x, by = blockIdx.y;
    const int ix = threadIdx.x, ty = threadIdx.y;
#pragma unroll
    for (int j = 0; j < 4; j++) {
        const int iy = ty * 4 + j;
        t[iy][ix] = W[(size_t)(by * 32 + iy) * Ncols + bx * 32 + ix];
    }
    __syncthreads();
#pragma unroll
    for (int j = 0; j < 4; j++) {
        const int iy = ty * 4 + j;
        const float x = t[ix][iy];
        const __nv_bfloat16 h = __float2bfloat16(x);
        const size_t o = (size_t)(bx * 32 + iy) * KT + by * 32 + ix;
        TH[o] = h;
        TL[o] = __float2bfloat16(x - __bfloat162float(h));
    }
}

// ---------------- validated attention chain (unchanged from R8) ----------------
__global__ void rope_kappa_naive(float* __restrict__ X, int H, int total_pairs)
{
    const int idx = blockIdx.x * blockDim.x + threadIdx.x;
    if (idx >= total_pairs) return;
    const int d = idx % 32;
    const int t = idx / 32;
    const int h = t % H;
    const int r = t / H;
    const int s = r % Sq;
    float* p = X + ((size_t)r * H + h) * 64;
    const float x1 = p[d], x2 = p[d + 32];
    const float invf = 1.0f / powf(10000.0f, (2.0f * (float)d) / 64.0f);
    const float ang = (float)s * invf;
    const float c = cosf(ang), sn = sinf(ang);
    const float o1 = x1 * c - x2 * sn;
    const float o2 = x2 * c + x1 * sn;
    p[d]      = o1 > 0.f ? o1 + 1.f : expf(o1);
    p[d + 32] = o2 > 0.f ? o2 + 1.f : expf(o2);
}

__global__ __launch_bounds__(256) void qg_tile(void)
{
    const int bh = blockIdx.x;
    const int b = bh / NHh, n = bh % NHh;
    const int d = threadIdx.x & 63, rr = threadIdx.x >> 6;
    float sum = 0.f;
    for (int s = rr; s < Sq; s += 4)
        sum += g_Qp[((size_t)(b * Sq + s)) * 2048 + n * 64 + d];
    __shared__ float sm[4][64];
    sm[rr][d] = sum;
    __syncthreads();
    if (threadIdx.x < 64) {
        const int dd = threadIdx.x;
        g_Qg[bh * 64 + dd] = (sm[0][dd] + sm[1][dd] + sm[2][dd] + sm[3][dd]) / (float)Sq;
    }
}

__global__ void logits_naive(void)
{
    const int idx = blockIdx.x * blockDim.x + threadIdx.x;
    if (idx >= 64 * Sq) return;
    const int s = idx % Sq, bh = idx / Sq;
    const int b = bh / NHh, n = bh % NHh, kn = n / 4;
    const float* row = g_Kp + ((size_t)(b * Sq + s)) * 512 + kn * 64;
    const float* qg  = g_Qg + bh * 64;
    float acc = 0.f;
    for (int d = 0; d < 64; d++) acc += row[d] * qg[d];
    g_alpha[idx] = acc;
}

__global__ __launch_bounds__(256) void softmax_naive(void)
{
    const int bh = blockIdx.x;
    float* l = g_alpha + (size_t)bh * Sq;
    __shared__ float sh[256];
    const int tid = threadIdx.x;
    float m = -1e30f;
    for (int s = tid; s < Sq; s += 256) m = fmaxf(m, l[s]);
    sh[tid] = m;
    __syncthreads();
    for (int st = 128; st; st >>= 1) {
        if (tid < st) sh[tid] = fmaxf(sh[tid], sh[tid + st]);
        __syncthreads();
    }
    m = sh[0];
    __syncthreads();
    float sum = 0.f;
    for (int s = tid; s < Sq; s += 256) sum += expf(l[s] - m);
    sh[tid] = sum;
    __syncthreads();
    for (int st = 128; st; st >>= 1) {
        if (tid < st) sh[tid] += sh[tid + st];
        __syncthreads();
    }
    const float scale = (float)Sq / sh[0];
    for (int s = tid; s < Sq; s += 256) l[s] = expf(l[s] - m) * scale;
}

__global__ __launch_bounds__(256) void outer_tile(void)
{
    const int split = blockIdx.x, bh = blockIdx.y;
    const int b = bh / NHh, n = bh % NHh, kn = n / 4;
    const float* al = g_alpha + (size_t)bh * Sq;
    __shared__ float Ks[32][68];
    __shared__ float Vs[32][68];
    const int tid = threadIdx.x;
    const int d0 = (tid >> 4) * 4, f0 = (tid & 15) * 4;
    const int sr = tid >> 3;
    const int c8 = (tid & 7) * 8;
    float acc[4][4] = {};
    const int s_begin = split * (Sq / OSPL);
    const int s_end   = s_begin + (Sq / OSPL);
    for (int s0 = s_begin; s0 < s_end; s0 += 32) {
        __syncthreads();
        {
            const float a = al[s0 + sr];
            const size_t base = ((size_t)(b * Sq + s0 + sr)) * 512 + kn * 64 + c8;
            float4 k0 = *(const float4*)(g_Kp + base);
            float4 k1 = *(const float4*)(g_Kp + base + 4);
            float4 v0 = *(const float4*)(g_Vp + base);
            float4 v1 = *(const float4*)(g_Vp + base + 4);
            k0.x *= a; k0.y *= a; k0.z *= a; k0.w *= a;
            k1.x *= a; k1.y *= a; k1.z *= a; k1.w *= a;
            *(float4*)&Ks[sr][c8]     = k0;
            *(float4*)&Ks[sr][c8 + 4] = k1;
            *(float4*)&Vs[sr][c8]     = v0;
            *(float4*)&Vs[sr][c8 + 4] = v1;
        }
        __syncthreads();
#pragma unroll 8
        for (int ss = 0; ss < 32; ss++) {
            float4 k4 = *(const float4*)&Ks[ss][d0];
            float4 v4 = *(const float4*)&Vs[ss][f0];
            float kr[4] = {k4.x, k4.y, k4.z, k4.w};
            float vr[4] = {v4.x, v4.y, v4.z, v4.w};
#pragma unroll
            for (int i = 0; i < 4; i++)
#pragma unroll
                for (int j = 0; j < 4; j++)
                    acc[i][j] = fmaf(kr[i], vr[j], acc[i][j]);
        }
    }
    float* Mo = g_Mpart + ((size_t)split * 64 + bh) * 4096;
#pragma unroll
    for (int i = 0; i < 4; i++)
#pragma unroll
        for (int j = 0; j < 4; j++)
            Mo[(d0 + i) * 64 + (f0 + j)] = acc[i][j];
}

__global__ void reduce_M(void)
{
    const int idx = blockIdx.x * blockDim.x + threadIdx.x;
    if (idx >= 64 * 4096) return;
    float s = 0.f;
#pragma unroll
    for (int k = 0; k < OSPL; k++) s += g_Mpart[(size_t)k * 64 * 4096 + idx];
    g_M[idx] = s;
}

// apply: ctx = Xphi * (Qk @ M), emitted as bf16 hi/lo for the Wo GEMM
__global__ void apply_vec4(void)
{
    const size_t q4 = (size_t)blockIdx.x * blockDim.x + threadIdx.x;
    if (q4 >= (size_t)Rrows * 2048 / 4) return;
    const size_t e = q4 * 4;
    const int c = (int)(e % 2048);
    const size_t r = e / 2048;
    const int n = c >> 6, f0 = c & 63;
    const int b = (int)(r / Sq);
    const int bh = b * NHh + n;
    const float* q = g_Qp + r * 2048 + n * 64;
    const float* m = g_M + (size_t)bh * 4096;
    float4 acc = {0.f, 0.f, 0.f, 0.f};
#pragma unroll 8
    for (int d = 0; d < 64; d++) {
        const float qd = q[d];
        float4 m4 = *(const float4*)(m + d * 64 + f0);
        acc.x = fmaf(qd, m4.x, acc.x);
        acc.y = fmaf(qd, m4.y, acc.y);
        acc.z = fmaf(qd, m4.z, acc.z);
        acc.w = fmaf(qd, m4.w, acc.w);
    }
    float4 xp = *(const float4*)(g_Xphi + e);
    const float v[4] = { acc.x * xp.x, acc.y * xp.y, acc.z * xp.z, acc.w * xp.w };
#pragma unroll
    for (int i = 0; i < 4; i++) {
        const __nv_bfloat16 hv = __float2bfloat16(v[i]);
        g_ctxh[e + i] = hv;
        g_ctxl[e + i] = __float2bfloat16(v[i] - __bfloat162float(hv));
    }
}

// ---------------- launch ----------------
extern "C" void kernel_launch(void* const* d_in, const int* in_sizes, int n_in,
                              void* d_out, int out_size)
{
    int hidx = -1, w4[3], n4 = 0, w1[2], n1 = 0;
    for (int i = 0; i < n_in; i++) {
        if (in_sizes[i] == 16777216) hidx = i;
        else if (in_sizes[i] == 4194304 && n4 < 3) w4[n4++] = i;
        else if (in_sizes[i] == 1048576 && n1 < 2) w1[n1++] = i;
    }
    const bool alpha_order = (w1[0] < w4[0]);
    const float* h    = (const float*)d_in[hidx];
    const float* Wq   = (const float*)d_in[alpha_order ? w4[2] : w4[0]];
    const float* Wphi = (const float*)d_in[w4[1]];
    const float* Wo   = (const float*)d_in[alpha_order ? w4[0] : w4[2]];
    const float* Wk   = (const float*)d_in[w1[0]];
    const float* Wv   = (const float*)d_in[w1[1]];
    float* out = (float*)d_out;

    static bool init = false;
    static float *Qp, *Kp, *Vp, *Xphi;
    static __nv_bfloat16 *hh, *hl, *ctxh, *ctxl;
    static __nv_bfloat16 *Wqth, *Wqtl, *Wkth, *Wktl, *Wvth, *Wvtl, *Wpth, *Wptl, *Woth, *Wotl;
    if (!init) {
        init = true;
        cudaGetSymbolAddress((void**)&Qp,   g_Qp);
        cudaGetSymbolAddress((void**)&Kp,   g_Kp);
        cudaGetSymbolAddress((void**)&Vp,   g_Vp);
        cudaGetSymbolAddress((void**)&Xphi, g_Xphi);
        cudaGetSymbolAddress((void**)&hh,   g_hh);
        cudaGetSymbolAddress((void**)&hl,   g_hl);
        cudaGetSymbolAddress((void**)&ctxh, g_ctxh);
        cudaGetSymbolAddress((void**)&ctxl, g_ctxl);
        cudaGetSymbolAddress((void**)&Wqth, g_Wqth); cudaGetSymbolAddress((void**)&Wqtl, g_Wqtl);
        cudaGetSymbolAddress((void**)&Wkth, g_Wkth); cudaGetSymbolAddress((void**)&Wktl, g_Wktl);
        cudaGetSymbolAddress((void**)&Wvth, g_Wvth); cudaGetSymbolAddress((void**)&Wvtl, g_Wvtl);
        cudaGetSymbolAddress((void**)&Wpth, g_Wpth); cudaGetSymbolAddress((void**)&Wptl, g_Wptl);
        cudaGetSymbolAddress((void**)&Woth, g_Woth); cudaGetSymbolAddress((void**)&Wotl, g_Wotl);
        cudaFuncSetAttribute(gemm_mma, cudaFuncAttributeMaxDynamicSharedMemorySize, 81920);
    }

    // convert inputs to bf16 splits (h K-major; weights transposed to [N, K])
    split_bf16<<<(16777216 + 255) / 256, 256>>>(h, hh, hl, 16777216);
    splitT_bf16<<<dim3(2048/32, KT/32), dim3(32, 8)>>>(Wq,   Wqth, Wqtl, 2048);
    splitT_bf16<<<dim3( 512/32, KT/32), dim3(32, 8)>>>(Wk,   Wkth, Wktl,  512);
    splitT_bf16<<<dim3( 512/32, KT/32), dim3(32, 8)>>>(Wv,   Wvth, Wvtl,  512);
    splitT_bf16<<<dim3(2048/32, KT/32), dim3(32, 8)>>>(Wphi, Wpth, Wptl, 2048);
    splitT_bf16<<<dim3(2048/32, KT/32), dim3(32, 8)>>>(Wo,   Woth, Wotl, 2048);

    // tensor-core (HMMA) projections
    gemm_mma<<<dim3(2048/128, Rrows/128), 256, 81920>>>(hh, hl, Wqth, Wqtl, Qp,   2048);
    gemm_mma<<<dim3( 512/128, Rrows/128), 256, 81920>>>(hh, hl, Wkth, Wktl, Kp,    512);
    gemm_mma<<<dim3( 512/128, Rrows/128), 256, 81920>>>(hh, hl, Wvth, Wvtl, Vp,    512);
    gemm_mma<<<dim3(2048/128, Rrows/128), 256, 81920>>>(hh, hl, Wpth, Wptl, Xphi, 2048);

    // attention chain (validated)
    {
        const int totQ = Rrows * NHh  * 32;
        const int totK = Rrows * NKVh * 32;
        rope_kappa_naive<<<(totQ + 255)/256, 256>>>(Qp, NHh,  totQ);
        rope_kappa_naive<<<(totK + 255)/256, 256>>>(Kp, NKVh, totK);
    }
    qg_tile<<<64, 256>>>();
    logits_naive<<<(64*Sq + 255)/256, 256>>>();
    softmax_naive<<<64, 256>>>();
    outer_tile<<<dim3(OSPL, 64), 256>>>();
    reduce_M<<<(64*4096 + 255)/256, 256>>>();
    apply_vec4<<<(int)(((size_t)Rrows*2048/4 + 255)/256), 256>>>();

    // output projection (HMMA)
    gemm_mma<<<dim3(2048/128, Rrows/128), 256, 81920>>>(ctxh, ctxl, Woth, Wotl, out, 2048);
}